// round 13
// baseline (speedup 1.0000x reference)
#include <cuda_runtime.h>
#include <cuda_bf16.h>
#include <cstdint>
#include <math.h>

// ---------------------------------------------------------------------------
// TopDown FPN (DCNv2 levels 3..1 + plain conv level 0).
// Tensor-core GEMMs (mma.sync bf16, fp32 accum) with hi/lo bf16 split:
//     C = Ahi*Bhi + Ahi*Blo + Alo*Bhi
// Implicit im2col fused into the GEMM B-tile fill for all REGULAR convs
// (level-0 main + all offset convs): B is read fp32 straight from the level
// input (L2-resident) and split in-kernel. Deformable mains use explicit
// fp32 cols from dcols; the GEMM splits those in-kernel too.
// R12 fix: helper `sbA` was defined below its use -> inlined at call site.
// ---------------------------------------------------------------------------

#define CIN   256
#define COUT  256
#define KK    2304      // 256*9
#define KT    72        // K iterations of BK=32

// smem per buffer: Ahi[128][40] Alo[128][40] Bhi[32][136] Blo[32][136]
#define A_TILE_B   10240      // 128*40*2
#define B_TILE_B   8704       // 32*136*2
#define BUF_B      37888
#define GEMM_SMEM  (2 * BUF_B)

// ---- scratch (static device globals; no allocation anywhere) --------------
__device__ float g_s[2 * 256 * 96 * 96];
__device__ float g_off[27 * 4608];
__device__ float g_part[5 * 1024 * 1024];
__device__ __align__(16) float g_cols[(size_t)2304 * 4608];   // dcols (lvl1 max)
__device__ __align__(16) __nv_bfloat16 g_whi[4][256 * 2304];
__device__ __align__(16) __nv_bfloat16 g_wlo[4][256 * 2304];
__device__ __align__(16) __nv_bfloat16 g_owhi[3][27 * 2304];
__device__ __align__(16) __nv_bfloat16 g_owlo[3][27 * 2304];

// ---------------------------------------------------------------------------
// PTX helpers (sm_80-era, valid on base sm_103 target)
// ---------------------------------------------------------------------------
__device__ __forceinline__ uint32_t smem_u32(const void* p) {
    uint32_t a;
    asm("{ .reg .u64 t; cvta.to.shared.u64 t, %1; cvt.u32.u64 %0, t; }"
        : "=r"(a) : "l"(p));
    return a;
}
__device__ __forceinline__ void cp16(uint32_t dst, const void* src, bool ok) {
    int sz = ok ? 16 : 0;
    asm volatile("cp.async.ca.shared.global [%0], [%1], 16, %2;"
                 :: "r"(dst), "l"(src), "r"(sz) : "memory");
}
#define CP_COMMIT() asm volatile("cp.async.commit_group;" ::: "memory")
#define CP_WAIT1()  asm volatile("cp.async.wait_group 1;"  ::: "memory")
#define CP_WAIT0()  asm volatile("cp.async.wait_group 0;"  ::: "memory")

__device__ __forceinline__ void ldsm_x4(uint32_t* r, uint32_t a) {
    asm volatile("ldmatrix.sync.aligned.m8n8.x4.shared.b16 {%0,%1,%2,%3}, [%4];"
                 : "=r"(r[0]), "=r"(r[1]), "=r"(r[2]), "=r"(r[3]) : "r"(a));
}
__device__ __forceinline__ void ldsm_x2t(uint32_t* r, uint32_t a) {
    asm volatile("ldmatrix.sync.aligned.m8n8.x2.trans.shared.b16 {%0,%1}, [%2];"
                 : "=r"(r[0]), "=r"(r[1]) : "r"(a));
}
__device__ __forceinline__ void mma16816(float* d, const uint32_t* a,
                                         const uint32_t* b) {
    asm volatile(
        "mma.sync.aligned.m16n8k16.row.col.f32.bf16.bf16.f32 "
        "{%0,%1,%2,%3}, {%4,%5,%6,%7}, {%8,%9}, {%0,%1,%2,%3};"
        : "+f"(d[0]), "+f"(d[1]), "+f"(d[2]), "+f"(d[3])
        : "r"(a[0]), "r"(a[1]), "r"(a[2]), "r"(a[3]), "r"(b[0]), "r"(b[1]));
}
__device__ __forceinline__ uint32_t pack_bf16x2(float a, float b) {
    __nv_bfloat162 t;
    t.x = __float2bfloat16(a);
    t.y = __float2bfloat16(b);
    uint32_t r;
    memcpy(&r, &t, 4);
    return r;
}

// ---------------------------------------------------------------------------
// glue kernels
// ---------------------------------------------------------------------------
__global__ void addup_kernel(const float* __restrict__ x,
                             const float* __restrict__ tp,
                             float* __restrict__ s, int H, int W)
{
    int idx = blockIdx.x * blockDim.x + threadIdx.x;
    int HW = H * W;
    int total = 2 * CIN * HW;
    if (idx >= total) return;
    int bc = idx / HW;
    int hw = idx - bc * HW;
    int h = hw / W, w = hw - h * W;
    int Wp = W >> 1;
    int HWp = (H >> 1) * Wp;
    s[idx] = x[idx] + tp[(size_t)bc * HWp + (h >> 1) * Wp + (w >> 1)];
}

// deformable cols -> fp32, layout [(ci*9+k)][N]
__global__ void dcols_kernel(const float* __restrict__ s,
                             const float* __restrict__ off,
                             float* __restrict__ cols,
                             int H, int W, int N)
{
    int idx = blockIdx.x * blockDim.x + threadIdx.x;
    if (idx >= CIN * N) return;
    int ci = idx / N;
    int p  = idx - ci * N;
    int HW = H * W;
    int b  = p / HW;
    int hw = p - b * HW;
    int h = hw / W, w = hw - h * W;
    const float* sp = s + ((size_t)b * CIN + ci) * HW;
    float* cb = cols + (size_t)ci * 9 * N + p;
#pragma unroll
    for (int k = 0; k < 9; ++k) {
        float dy = off[(size_t)(2 * k)     * N + p];
        float dx = off[(size_t)(2 * k + 1) * N + p];
        float m  = off[(size_t)(18 + k)    * N + p];
        float py = (float)(h - 1 + k / 3) + dy;
        float px = (float)(w - 1 + k % 3) + dx;
        float y0f = floorf(py), x0f = floorf(px);
        int   y0 = (int)y0f,   x0 = (int)x0f;
        float wy1 = py - y0f,  wx1 = px - x0f;
        float wy0 = 1.f - wy1, wx0 = 1.f - wx1;
        float v = 0.f;
        if ((unsigned)y0 < (unsigned)H) {
            const float* r0 = sp + y0 * W;
            if ((unsigned)x0       < (unsigned)W) v += r0[x0]     * (wy0 * wx0);
            if ((unsigned)(x0 + 1) < (unsigned)W) v += r0[x0 + 1] * (wy0 * wx1);
        }
        if ((unsigned)(y0 + 1) < (unsigned)H) {
            const float* r1 = sp + (y0 + 1) * W;
            if ((unsigned)x0       < (unsigned)W) v += r1[x0]     * (wy1 * wx0);
            if ((unsigned)(x0 + 1) < (unsigned)W) v += r1[x0 + 1] * (wy1 * wx1);
        }
        cb[(size_t)k * N] = v * m;
    }
}

// fp32 -> bf16 hi/lo elementwise (weights, [M][K] row-major preserved)
__global__ void wsplit_kernel(const float* __restrict__ w,
                              __nv_bfloat16* __restrict__ hi,
                              __nv_bfloat16* __restrict__ lo, int n)
{
    int i = blockIdx.x * blockDim.x + threadIdx.x;
    if (i >= n) return;
    float v = w[i];
    __nv_bfloat16 h = __float2bfloat16(v);
    hi[i] = h;
    lo[i] = __float2bfloat16(v - __bfloat162float(h));
}

// ---------------------------------------------------------------------------
// Tensor-core GEMM, 128x128 per CTA, BK=32, 8 warps (2m x 4n).
// A: pre-split bf16 hi/lo [M][2304] via cp.async.
// B: fp32 source, split in-kernel into Bhi/Blo smem tiles.
//   IMPL=true : implicit im2col from level input s[(b*256+ci)*HW + y*W + x]
//   IMPL=false: explicit fp32 cols [K][Ntot]
// S==1: fused bias + NCHW epilogue.  S>1: fp32 partials at C + z*M*Ntot.
// ---------------------------------------------------------------------------
template <bool IMPL>
__global__ __launch_bounds__(256)
void gemm_kernel(const __nv_bfloat16* __restrict__ Ahi,
                 const __nv_bfloat16* __restrict__ Alo,
                 const float* __restrict__ Bsrc,
                 const float* __restrict__ bias,
                 float* __restrict__ C,
                 int M, int Ntot, int H, int W, int S)
{
    extern __shared__ __align__(16) char smem[];
    const uint32_t sb = smem_u32(smem);
    const int tid  = threadIdx.x;
    const int lane = tid & 31;
    const int wid  = tid >> 5;
    const int warpM = wid & 1;
    const int warpN = wid >> 1;
    const int mBase = blockIdx.y << 7;
    const int nBase = blockIdx.x << 7;
    const int HW = H * W;
    const int iters  = KT / S;
    const int kStart = blockIdx.z * iters * 32;

    float acc[4][4][4];
#pragma unroll
    for (int mi = 0; mi < 4; ++mi)
#pragma unroll
        for (int ni = 0; ni < 4; ++ni)
#pragma unroll
            for (int q = 0; q < 4; ++q) acc[mi][ni][q] = 0.f;

    // ---- per-thread B-fill geometry: 8 x (1 k-row, 2 n-cols) ----
    const int krow0 = tid >> 6;                 // 0..3
    const int n0    = nBase + ((tid & 63) << 1);
    int b0 = 0, h0 = 0, w0 = 0, b1 = 0, h1 = 0, w1 = 0;
    bool vn0 = false, vn1 = false;
    if (IMPL) {
        int n1 = n0 + 1;
        vn0 = n0 < Ntot;
        vn1 = n1 < Ntot;
        int bb = n0 / HW, hw = n0 - bb * HW;
        b0 = bb; h0 = hw / W; w0 = hw - h0 * W;
        bb = n1 / HW; hw = n1 - bb * HW;
        b1 = bb; h1 = hw / W; w1 = hw - h1 * W;
    }

    // ---- A loader: 1024 x 16B cp.async chunks ----
    auto loadA = [&](int buf, int it) {
        const int kb = kStart + it * 32;
        const uint32_t base = sb + buf * BUF_B;
#pragma unroll
        for (int p = 0; p < 4; ++p) {
            const int u = tid + (p << 8);
            const __nv_bfloat16* srcb = (u < 512) ? Ahi : Alo;
            const int v = u & 511;
            const int row = v >> 2, c = v & 3;
            const int gr = mBase + row;
            const bool ok = gr < M;
            const void* src = srcb + (size_t)(ok ? gr : 0) * KK + kb + c * 8;
            uint32_t dst = base + ((u < 512) ? 0u : (uint32_t)A_TILE_B)
                         + row * 80 + c * 16;
            cp16(dst, src, ok);
        }
    };

    // ---- B prefetch into registers (16 fp32 per thread) ----
    float breg[16];
    auto loadB = [&](int it) {
        const int kb = kStart + it * 32 + krow0;
#pragma unroll
        for (int j = 0; j < 8; ++j) {
            const int k = kb + j * 4;
            if (IMPL) {
                const int ci = k / 9;
                const int r  = k - ci * 9;
                const int ky = r / 3, kx = r - ky * 3;
                const float* base = Bsrc + (size_t)ci * HW;
                float v0 = 0.f, v1 = 0.f;
                {
                    int y = h0 + ky - 1, x = w0 + kx - 1;
                    if (vn0 && (unsigned)y < (unsigned)H && (unsigned)x < (unsigned)W)
                        v0 = base[(size_t)b0 * CIN * HW + y * W + x];
                }
                {
                    int y = h1 + ky - 1, x = w1 + kx - 1;
                    if (vn1 && (unsigned)y < (unsigned)H && (unsigned)x < (unsigned)W)
                        v1 = base[(size_t)b1 * CIN * HW + y * W + x];
                }
                breg[2 * j]     = v0;
                breg[2 * j + 1] = v1;
            } else {
                float2 f = make_float2(0.f, 0.f);
                if (n0 < Ntot)
                    f = *(const float2*)(Bsrc + (size_t)k * Ntot + n0);
                breg[2 * j]     = f.x;
                breg[2 * j + 1] = f.y;
            }
        }
    };

    // ---- B store: split to bf16 hi/lo smem tiles ----
    auto storeB = [&](int buf) {
        char* bHi = smem + buf * BUF_B + 2 * A_TILE_B;
        char* bLo = bHi + B_TILE_B;
        const int coff = (tid & 63) << 2;   // byte offset within 272B row
#pragma unroll
        for (int j = 0; j < 8; ++j) {
            const int krow = krow0 + j * 4;
            const float v0 = breg[2 * j], v1 = breg[2 * j + 1];
            const float h0f = __bfloat162float(__float2bfloat16(v0));
            const float h1f = __bfloat162float(__float2bfloat16(v1));
            *(uint32_t*)(bHi + krow * 272 + coff) = pack_bf16x2(v0, v1);
            *(uint32_t*)(bLo + krow * 272 + coff) = pack_bf16x2(v0 - h0f, v1 - h1f);
        }
    };

    // per-thread fragment address offsets (validated in R9)
    const uint32_t aoff = ((warpM << 6) + (lane & 15)) * 80 + (lane >> 4) * 16;
    const uint32_t boff = (lane & 15) * 272 + (warpN << 6);

    auto compute = [&](int buf) {
        const uint32_t base = sb + buf * BUF_B;
        const uint32_t aHi = base;
        const uint32_t aLo = base + A_TILE_B;
        const uint32_t bHi = base + 2 * A_TILE_B;
        const uint32_t bLo = bHi + B_TILE_B;
#pragma unroll
        for (int k16 = 0; k16 < 2; ++k16) {
            uint32_t aF[4][4], bF[4][2];
#pragma unroll
            for (int mi = 0; mi < 4; ++mi)
                ldsm_x4(aF[mi], aHi + aoff + mi * (16 * 80) + k16 * 32);
#pragma unroll
            for (int ni = 0; ni < 4; ++ni)
                ldsm_x2t(bF[ni], bLo + boff + ni * 16 + k16 * (16 * 272));
#pragma unroll
            for (int mi = 0; mi < 4; ++mi)
#pragma unroll
                for (int ni = 0; ni < 4; ++ni)
                    mma16816(acc[mi][ni], aF[mi], bF[ni]);
#pragma unroll
            for (int ni = 0; ni < 4; ++ni)
                ldsm_x2t(bF[ni], bHi + boff + ni * 16 + k16 * (16 * 272));
#pragma unroll
            for (int mi = 0; mi < 4; ++mi)
#pragma unroll
                for (int ni = 0; ni < 4; ++ni)
                    mma16816(acc[mi][ni], aF[mi], bF[ni]);
#pragma unroll
            for (int mi = 0; mi < 4; ++mi)
                ldsm_x4(aF[mi], aLo + aoff + mi * (16 * 80) + k16 * 32);
#pragma unroll
            for (int mi = 0; mi < 4; ++mi)
#pragma unroll
                for (int ni = 0; ni < 4; ++ni)
                    mma16816(acc[mi][ni], aF[mi], bF[ni]);
        }
    };

    // ---- mainloop ----
    loadA(0, 0);
    CP_COMMIT();
    loadB(0);
    for (int it = 0; it < iters; ++it) {
        const int buf = it & 1;
        storeB(buf);                       // breg for `it` -> smem
        if (it + 1 < iters) {
            loadA(buf ^ 1, it + 1);
            CP_COMMIT();
            loadB(it + 1);                 // refill breg for it+1
            CP_WAIT1();                    // A for current buf done
        } else {
            CP_WAIT0();
        }
        __syncthreads();
        compute(buf);
        __syncthreads();
    }

    // ---- epilogue ----
#pragma unroll
    for (int mi = 0; mi < 4; ++mi) {
        const int r0 = mBase + (warpM << 6) + mi * 16 + (lane >> 2);
#pragma unroll
        for (int ni = 0; ni < 4; ++ni) {
            const int c0 = nBase + (warpN << 5) + ni * 8 + ((lane & 3) << 1);
            const float* a = acc[mi][ni];
#pragma unroll
            for (int half = 0; half < 2; ++half) {
                const int row = r0 + half * 8;
                if (row >= M || c0 >= Ntot) continue;
                const float v0 = a[half * 2 + 0];
                const float v1 = a[half * 2 + 1];
                if (S == 1) {
                    const float bv = bias[row];
                    int bb = c0 / HW;
                    int hw = c0 - bb * HW;
                    float* o = C + ((size_t)bb * COUT + row) * HW + hw;
                    o[0] = v0 + bv;
                    o[1] = v1 + bv;
                } else {
                    float* P = C + (size_t)blockIdx.z * M * Ntot
                             + (size_t)row * Ntot + c0;
                    P[0] = v0;
                    P[1] = v1;
                }
            }
        }
    }
}

// ---------------------------------------------------------------------------
// split-K reduces (deterministic; bias/sigmoid/NCHW fused)
// ---------------------------------------------------------------------------
__global__ void reduce_off_kernel(const float* __restrict__ P,
                                  const float* __restrict__ ob,
                                  float* __restrict__ off, int N, int S)
{
    int idx = blockIdx.x * blockDim.x + threadIdx.x;
    if (idx >= 27 * N) return;
    int r = idx / N;
    float v = ob[r];
    for (int s = 0; s < S; ++s)
        v += P[(size_t)s * 27 * N + idx];
    if (r >= 18)
        v = 1.f / (1.f + expf(-v));
    off[idx] = v;
}

__global__ void reduce_main_kernel(const float* __restrict__ P,
                                   const float* __restrict__ bias,
                                   float* __restrict__ out, int N, int HW, int S)
{
    int idx = blockIdx.x * blockDim.x + threadIdx.x;
    if (idx >= COUT * N) return;
    int row = idx / N;
    int col = idx - row * N;
    float v = bias[row];
    for (int s = 0; s < S; ++s)
        v += P[(size_t)s * COUT * N + idx];
    int bb = col / HW;
    int hw = col - bb * HW;
    out[((size_t)bb * COUT + row) * HW + hw] = v;
}

// ---------------------------------------------------------------------------
// Host side
// ---------------------------------------------------------------------------
extern "C" void kernel_launch(void* const* d_in, const int* in_sizes, int n_in,
                              void* d_out, int out_size)
{
    const float* xs[4]  = {nullptr, nullptr, nullptr, nullptr};
    const float* ws[4]  = {nullptr, nullptr, nullptr, nullptr};
    const float* bs[4]  = {nullptr, nullptr, nullptr, nullptr};
    const float* ows[3] = {nullptr, nullptr, nullptr};
    const float* obs[3] = {nullptr, nullptr, nullptr};
    int wi = 0, bi = 0, owi = 0, obi = 0;
    for (int i = 0; i < n_in; ++i) {
        const float* p = (const float*)d_in[i];
        switch (in_sizes[i]) {
            case 2 * 256 * 96 * 96: xs[0] = p; break;
            case 2 * 256 * 48 * 48: xs[1] = p; break;
            case 2 * 256 * 24 * 24: xs[2] = p; break;
            case 2 * 256 * 12 * 12: xs[3] = p; break;
            case 256 * 256 * 3 * 3: if (wi  < 4) ws[wi++]   = p; break;
            case 256:               if (bi  < 4) bs[bi++]   = p; break;
            case 27 * 256 * 3 * 3:  if (owi < 3) ows[owi++] = p; break;
            case 27:                if (obi < 3) obs[obi++] = p; break;
            default: break;
        }
    }

    float* out = (float*)d_out;
    float* s;    cudaGetSymbolAddress((void**)&s,    g_s);
    float* off;  cudaGetSymbolAddress((void**)&off,  g_off);
    float* part; cudaGetSymbolAddress((void**)&part, g_part);
    float* cols; cudaGetSymbolAddress((void**)&cols, g_cols);
    __nv_bfloat16* whi;  cudaGetSymbolAddress((void**)&whi,  g_whi);
    __nv_bfloat16* wlo;  cudaGetSymbolAddress((void**)&wlo,  g_wlo);
    __nv_bfloat16* owhi; cudaGetSymbolAddress((void**)&owhi, g_owhi);
    __nv_bfloat16* owlo; cudaGetSymbolAddress((void**)&owlo, g_owlo);

    cudaFuncSetAttribute(gemm_kernel<true>,
                         cudaFuncAttributeMaxDynamicSharedMemorySize, GEMM_SMEM);
    cudaFuncSetAttribute(gemm_kernel<false>,
                         cudaFuncAttributeMaxDynamicSharedMemorySize, GEMM_SMEM);

    const size_t OFF0 = 0;
    const size_t OFF1 = OFF0 + (size_t)2 * 256 * 96 * 96;
    const size_t OFF2 = OFF1 + (size_t)2 * 256 * 48 * 48;
    const size_t OFF3 = OFF2 + (size_t)2 * 256 * 24 * 24;
    const size_t outOff[4] = {OFF0, OFF1, OFF2, OFF3};

    // weight splits (cheap, deterministic, every call)
    for (int i = 0; i < 4; ++i)
        wsplit_kernel<<<(256 * KK + 255) / 256, 256>>>(
            ws[i], whi + (size_t)i * 256 * KK, wlo + (size_t)i * 256 * KK,
            256 * KK);
    for (int j = 0; j < 3; ++j)
        wsplit_kernel<<<(27 * KK + 255) / 256, 256>>>(
            ows[j], owhi + (size_t)j * 27 * KK, owlo + (size_t)j * 27 * KK,
            27 * KK);

    const int Hs[4]    = {96, 48, 24, 12};
    const int mainS[4] = {1, 3, 12, 36};   // divisors of 72; part fits 5M floats
    const int offS[4]  = {1, 6, 24, 72};

    // ---- levels 3, 2, 1: modulated deformable conv ----
    for (int lvl = 3; lvl >= 1; --lvl) {
        int H = Hs[lvl], W = H;
        int HW = H * W;
        int N = 2 * HW;

        const float* sin;
        if (lvl == 3) {
            sin = xs[3];
        } else {
            int total = 2 * CIN * HW;
            addup_kernel<<<(total + 255) / 256, 256>>>(
                xs[lvl], out + outOff[lvl + 1], s, H, W);
            sin = s;
        }

        // offset conv: implicit-im2col GEMM(splitK) -> reduce(+sigmoid)
        {
            int S = offS[lvl];
            dim3 grid((N + 127) / 128, 1, S);
            gemm_kernel<true><<<grid, 256, GEMM_SMEM>>>(
                owhi + (size_t)(lvl - 1) * 27 * KK,
                owlo + (size_t)(lvl - 1) * 27 * KK,
                sin, obs[lvl - 1], part, 27, N, H, W, S);
            reduce_off_kernel<<<(27 * N + 255) / 256, 256>>>(
                part, obs[lvl - 1], off, N, S);
        }

        // main conv: dcols(fp32) -> explicit GEMM(splitK) -> reduce(NCHW)
        dcols_kernel<<<(CIN * N + 255) / 256, 256>>>(sin, off, cols, H, W, N);
        {
            int S = mainS[lvl];
            dim3 grid((N + 127) / 128, 2, S);
            gemm_kernel<false><<<grid, 256, GEMM_SMEM>>>(
                whi + (size_t)lvl * 256 * KK, wlo + (size_t)lvl * 256 * KK,
                cols, bs[lvl], part, COUT, N, H, W, S);
            reduce_main_kernel<<<(COUT * N + 255) / 256, 256>>>(
                part, bs[lvl], out + outOff[lvl], N, HW, S);
        }
    }

    // ---- level 0: plain conv, implicit-im2col GEMM, fused epilogue ----
    {
        int H = 96, W = 96, HW = H * W, N = 2 * HW;
        int total = 2 * CIN * HW;
        addup_kernel<<<(total + 255) / 256, 256>>>(xs[0], out + OFF1, s, H, W);
        dim3 grid((N + 127) / 128, 2, 1);
        gemm_kernel<true><<<grid, 256, GEMM_SMEM>>>(
            whi, wlo, s, bs[0], out + OFF0, COUT, N, H, W, 1);
    }
}

// round 17
// speedup vs baseline: 1.2419x; 1.2419x over previous
#include <cuda_runtime.h>
#include <cuda_bf16.h>
#include <cstdint>
#include <math.h>

// ---------------------------------------------------------------------------
// TopDown FPN (DCNv2 levels 3..1 + plain conv level 0).
// R15 = R14 resubmit (infra failure last round; kernel never ran):
//   * R9 base (explicit bf16 hi/lo cols + cp.async tensor-core GEMM; 523us)
//   * grid transposed (x=m-tile, y=n-tile) so the two M-tiles sharing the
//     same B columns are co-resident -> B re-read hits L2, not DRAM
//   * __launch_bounds__(256,2) for 2 CTAs/SM on the GEMM
//   * retuned split-K factors (fuller waves, less partial traffic)
// GEMM math: C = Ahi*Bhi + Ahi*Blo + Alo*Bhi (bf16 hi/lo split, fp32 accum)
// ---------------------------------------------------------------------------

#define CIN   256
#define COUT  256
#define KK    2304      // 256*9
#define KT    72        // K iterations of BK=32

// smem per buffer: Ahi[128][40] Alo[128][40] Bhi[32][136] Blo[32][136]
#define A_TILE_B   10240      // 128*40*2
#define B_TILE_B   8704       // 32*136*2
#define BUF_B      37888
#define GEMM_SMEM  (2 * BUF_B)

// ---- scratch (static device globals; no allocation anywhere) --------------
__device__ float g_s[2 * 256 * 96 * 96];
__device__ float g_off[27 * 4608];
__device__ float g_part[6 * 1024 * 1024];
__device__ __align__(16) __nv_bfloat16 g_colshi[(size_t)2304 * 18432];
__device__ __align__(16) __nv_bfloat16 g_colslo[(size_t)2304 * 18432];
__device__ __align__(16) __nv_bfloat16 g_whi[4][256 * 2304];
__device__ __align__(16) __nv_bfloat16 g_wlo[4][256 * 2304];
__device__ __align__(16) __nv_bfloat16 g_owhi[3][27 * 2304];
__device__ __align__(16) __nv_bfloat16 g_owlo[3][27 * 2304];

// ---------------------------------------------------------------------------
// PTX helpers (sm_80-era, valid on base sm_103 target)
// ---------------------------------------------------------------------------
__device__ __forceinline__ uint32_t smem_u32(const void* p) {
    uint32_t a;
    asm("{ .reg .u64 t; cvta.to.shared.u64 t, %1; cvt.u32.u64 %0, t; }"
        : "=r"(a) : "l"(p));
    return a;
}
__device__ __forceinline__ void cp16(uint32_t dst, const void* src, bool ok) {
    int sz = ok ? 16 : 0;
    asm volatile("cp.async.ca.shared.global [%0], [%1], 16, %2;"
                 :: "r"(dst), "l"(src), "r"(sz) : "memory");
}
#define CP_COMMIT() asm volatile("cp.async.commit_group;" ::: "memory")
#define CP_WAIT1()  asm volatile("cp.async.wait_group 1;"  ::: "memory")

__device__ __forceinline__ void ldsm_x4(uint32_t* r, uint32_t a) {
    asm volatile("ldmatrix.sync.aligned.m8n8.x4.shared.b16 {%0,%1,%2,%3}, [%4];"
                 : "=r"(r[0]), "=r"(r[1]), "=r"(r[2]), "=r"(r[3]) : "r"(a));
}
__device__ __forceinline__ void ldsm_x2t(uint32_t* r, uint32_t a) {
    asm volatile("ldmatrix.sync.aligned.m8n8.x2.trans.shared.b16 {%0,%1}, [%2];"
                 : "=r"(r[0]), "=r"(r[1]) : "r"(a));
}
__device__ __forceinline__ void mma16816(float* d, const uint32_t* a,
                                         const uint32_t* b) {
    asm volatile(
        "mma.sync.aligned.m16n8k16.row.col.f32.bf16.bf16.f32 "
        "{%0,%1,%2,%3}, {%4,%5,%6,%7}, {%8,%9}, {%0,%1,%2,%3};"
        : "+f"(d[0]), "+f"(d[1]), "+f"(d[2]), "+f"(d[3])
        : "r"(a[0]), "r"(a[1]), "r"(a[2]), "r"(a[3]), "r"(b[0]), "r"(b[1]));
}

// ---------------------------------------------------------------------------
// glue kernels
// ---------------------------------------------------------------------------
__global__ void addup_kernel(const float* __restrict__ x,
                             const float* __restrict__ tp,
                             float* __restrict__ s, int H, int W)
{
    int idx = blockIdx.x * blockDim.x + threadIdx.x;
    int HW = H * W;
    int total = 2 * CIN * HW;
    if (idx >= total) return;
    int bc = idx / HW;
    int hw = idx - bc * HW;
    int h = hw / W, w = hw - h * W;
    int Wp = W >> 1;
    int HWp = (H >> 1) * Wp;
    s[idx] = x[idx] + tp[(size_t)bc * HWp + (h >> 1) * Wp + (w >> 1)];
}

__device__ __forceinline__ void split_store(__nv_bfloat16* hi,
                                            __nv_bfloat16* lo,
                                            size_t o, float v)
{
    __nv_bfloat16 h = __float2bfloat16(v);
    hi[o] = h;
    lo[o] = __float2bfloat16(v - __bfloat162float(h));
}

// im2col -> bf16 hi/lo, layout [(ci*9+k)][N], p = b*HW + hw contiguous
__global__ void im2col_kernel(const float* __restrict__ s,
                              __nv_bfloat16* __restrict__ hi,
                              __nv_bfloat16* __restrict__ lo,
                              int H, int W, int N)
{
    int idx = blockIdx.x * blockDim.x + threadIdx.x;
    if (idx >= CIN * N) return;
    int ci = idx / N;
    int p  = idx - ci * N;
    int HW = H * W;
    int b  = p / HW;
    int hw = p - b * HW;
    int h = hw / W, w = hw - h * W;
    const float* sp = s + ((size_t)b * CIN + ci) * HW;
    size_t base = (size_t)ci * 9 * N + p;
#pragma unroll
    for (int ky = 0; ky < 3; ++ky) {
        int y = h - 1 + ky;
#pragma unroll
        for (int kx = 0; kx < 3; ++kx) {
            int x = w - 1 + kx;
            float v = 0.f;
            if ((unsigned)y < (unsigned)H && (unsigned)x < (unsigned)W)
                v = sp[y * W + x];
            split_store(hi, lo, base + (size_t)(ky * 3 + kx) * N, v);
        }
    }
}

// deformable cols -> bf16 hi/lo, same layout
__global__ void dcols_kernel(const float* __restrict__ s,
                             const float* __restrict__ off,
                             __nv_bfloat16* __restrict__ hi,
                             __nv_bfloat16* __restrict__ lo,
                             int H, int W, int N)
{
    int idx = blockIdx.x * blockDim.x + threadIdx.x;
    if (idx >= CIN * N) return;
    int ci = idx / N;
    int p  = idx - ci * N;
    int HW = H * W;
    int b  = p / HW;
    int hw = p - b * HW;
    int h = hw / W, w = hw - h * W;
    const float* sp = s + ((size_t)b * CIN + ci) * HW;
    size_t base = (size_t)ci * 9 * N + p;
#pragma unroll
    for (int k = 0; k < 9; ++k) {
        float dy = off[(size_t)(2 * k)     * N + p];
        float dx = off[(size_t)(2 * k + 1) * N + p];
        float m  = off[(size_t)(18 + k)    * N + p];
        float py = (float)(h - 1 + k / 3) + dy;
        float px = (float)(w - 1 + k % 3) + dx;
        float y0f = floorf(py), x0f = floorf(px);
        int   y0 = (int)y0f,   x0 = (int)x0f;
        float wy1 = py - y0f,  wx1 = px - x0f;
        float wy0 = 1.f - wy1, wx0 = 1.f - wx1;
        float v = 0.f;
        if ((unsigned)y0 < (unsigned)H) {
            const float* r0 = sp + y0 * W;
            if ((unsigned)x0       < (unsigned)W) v += r0[x0]     * (wy0 * wx0);
            if ((unsigned)(x0 + 1) < (unsigned)W) v += r0[x0 + 1] * (wy0 * wx1);
        }
        if ((unsigned)(y0 + 1) < (unsigned)H) {
            const float* r1 = sp + (y0 + 1) * W;
            if ((unsigned)x0       < (unsigned)W) v += r1[x0]     * (wy1 * wx0);
            if ((unsigned)(x0 + 1) < (unsigned)W) v += r1[x0 + 1] * (wy1 * wx1);
        }
        split_store(hi, lo, base + (size_t)k * N, v * m);
    }
}

// fp32 -> bf16 hi/lo elementwise (weights, [M][K] row-major preserved)
__global__ void wsplit_kernel(const float* __restrict__ w,
                              __nv_bfloat16* __restrict__ hi,
                              __nv_bfloat16* __restrict__ lo, int n)
{
    int i = blockIdx.x * blockDim.x + threadIdx.x;
    if (i >= n) return;
    float v = w[i];
    __nv_bfloat16 h = __float2bfloat16(v);
    hi[i] = h;
    lo[i] = __float2bfloat16(v - __bfloat162float(h));
}

// ---------------------------------------------------------------------------
// Tensor-core GEMM: 128x128 per CTA, BK=32, 8 warps (2m x 4n, warp 64x32),
// mma.m16n8k16 bf16, cp.async double buffering, 2 CTAs/SM.
// Grid: (mTiles, nTiles, S) -- x = m so same-B CTAs are co-resident.
// A: [M][2304] hi/lo (row-major). B: [2304][Ntot] hi/lo (N contiguous).
// S==1: fused bias + NCHW epilogue.  S>1: fp32 partials at C + z*M*Ntot.
// ---------------------------------------------------------------------------
__global__ __launch_bounds__(256, 2)
void gemm_kernel(const __nv_bfloat16* __restrict__ Ahi,
                 const __nv_bfloat16* __restrict__ Alo,
                 const __nv_bfloat16* __restrict__ Bhi,
                 const __nv_bfloat16* __restrict__ Blo,
                 const float* __restrict__ bias,
                 float* __restrict__ C,
                 int M, int Ntot, int HW, int S)
{
    extern __shared__ __align__(16) char smem[];
    const uint32_t sb = smem_u32(smem);
    const int tid  = threadIdx.x;
    const int lane = tid & 31;
    const int wid  = tid >> 5;
    const int warpM = wid & 1;
    const int warpN = wid >> 1;
    const int mBase = blockIdx.x << 7;   // x = m-tile (grid transposed)
    const int nBase = blockIdx.y << 7;   // y = n-tile
    const int iters  = KT / S;
    const int kStart = blockIdx.z * iters * 32;

    float acc[4][4][4];
#pragma unroll
    for (int mi = 0; mi < 4; ++mi)
#pragma unroll
        for (int ni = 0; ni < 4; ++ni)
#pragma unroll
            for (int q = 0; q < 4; ++q) acc[mi][ni][q] = 0.f;

    // ---- tile loader (cp.async): 2048 x 16B chunks per buffer ----
    auto load_tiles = [&](int buf, int it) {
        const int kb = kStart + it * 32;
        const uint32_t base = sb + buf * BUF_B;
#pragma unroll
        for (int p = 0; p < 8; ++p) {
            const int u = tid + (p << 8);
            if (u < 1024) {                 // A tiles: 128 rows x 4 chunks
                const __nv_bfloat16* srcb = (u < 512) ? Ahi : Alo;
                const int v = u & 511;
                const int row = v >> 2, c = v & 3;
                const int gr = mBase + row;
                const bool ok = gr < M;
                const void* src = srcb + (size_t)(ok ? gr : 0) * KK + kb + c * 8;
                uint32_t dst = base + ((u < 512) ? 0u : (uint32_t)A_TILE_B)
                             + row * 80 + c * 16;
                cp16(dst, src, ok);
            } else {                        // B tiles: 32 k-rows x 16 chunks
                const __nv_bfloat16* srcb = (u < 1536) ? Bhi : Blo;
                const int v = u & 511;
                const int row = v >> 4, c = v & 15;
                const int gn = nBase + c * 8;
                const bool ok = gn < Ntot;
                const void* src = srcb + (size_t)(kb + row) * Ntot + (ok ? gn : 0);
                uint32_t dst = base + 2 * A_TILE_B + ((u < 1536) ? 0u : (uint32_t)B_TILE_B)
                             + row * 272 + c * 16;
                cp16(dst, src, ok);
            }
        }
    };

    // per-thread fragment address offsets (validated R9)
    const uint32_t aoff = ((warpM << 6) + (lane & 15)) * 80 + (lane >> 4) * 16;
    const uint32_t boff = (lane & 15) * 272 + (warpN << 6);

    auto compute = [&](int buf) {
        const uint32_t base = sb + buf * BUF_B;
        const uint32_t aHi = base;
        const uint32_t aLo = base + A_TILE_B;
        const uint32_t bHi = base + 2 * A_TILE_B;
        const uint32_t bLo = bHi + B_TILE_B;
#pragma unroll
        for (int k16 = 0; k16 < 2; ++k16) {
            uint32_t aF[4][4], bF[4][2];
#pragma unroll
            for (int mi = 0; mi < 4; ++mi)
                ldsm_x4(aF[mi], aHi + aoff + mi * (16 * 80) + k16 * 32);
#pragma unroll
            for (int ni = 0; ni < 4; ++ni)
                ldsm_x2t(bF[ni], bLo + boff + ni * 16 + k16 * (16 * 272));
#pragma unroll
            for (int mi = 0; mi < 4; ++mi)
#pragma unroll
                for (int ni = 0; ni < 4; ++ni)
                    mma16816(acc[mi][ni], aF[mi], bF[ni]);
#pragma unroll
            for (int ni = 0; ni < 4; ++ni)
                ldsm_x2t(bF[ni], bHi + boff + ni * 16 + k16 * (16 * 272));
#pragma unroll
            for (int mi = 0; mi < 4; ++mi)
#pragma unroll
                for (int ni = 0; ni < 4; ++ni)
                    mma16816(acc[mi][ni], aF[mi], bF[ni]);
#pragma unroll
            for (int mi = 0; mi < 4; ++mi)
                ldsm_x4(aF[mi], aLo + aoff + mi * (16 * 80) + k16 * 32);
#pragma unroll
            for (int mi = 0; mi < 4; ++mi)
#pragma unroll
                for (int ni = 0; ni < 4; ++ni)
                    mma16816(acc[mi][ni], aF[mi], bF[ni]);
        }
    };

    // ---- mainloop (double buffered) ----
    load_tiles(0, 0);
    CP_COMMIT();
    for (int it = 0; it < iters; ++it) {
        if (it + 1 < iters) load_tiles((it + 1) & 1, it + 1);
        CP_COMMIT();
        CP_WAIT1();
        __syncthreads();
        compute(it & 1);
        __syncthreads();
    }

    // ---- epilogue ----
#pragma unroll
    for (int mi = 0; mi < 4; ++mi) {
        const int r0 = mBase + (warpM << 6) + mi * 16 + (lane >> 2);
#pragma unroll
        for (int ni = 0; ni < 4; ++ni) {
            const int c0 = nBase + (warpN << 5) + ni * 8 + ((lane & 3) << 1);
            const float* a = acc[mi][ni];
#pragma unroll
            for (int half = 0; half < 2; ++half) {
                const int row = r0 + half * 8;
                if (row >= M || c0 >= Ntot) continue;
                const float v0 = a[half * 2 + 0];
                const float v1 = a[half * 2 + 1];
                if (S == 1) {
                    const float bv = bias[row];
                    int bb = c0 / HW;
                    int hw = c0 - bb * HW;
                    float* o = C + ((size_t)bb * COUT + row) * HW + hw;
                    o[0] = v0 + bv;
                    o[1] = v1 + bv;   // c0 even, HW even -> same image row
                } else {
                    float* P = C + (size_t)blockIdx.z * M * Ntot
                             + (size_t)row * Ntot + c0;
                    P[0] = v0;
                    P[1] = v1;
                }
            }
        }
    }
}

// ---------------------------------------------------------------------------
// split-K reduces (deterministic; bias/sigmoid/NCHW fused)
// ---------------------------------------------------------------------------
__global__ void reduce_off_kernel(const float* __restrict__ P,
                                  const float* __restrict__ ob,
                                  float* __restrict__ off, int N, int S)
{
    int idx = blockIdx.x * blockDim.x + threadIdx.x;
    if (idx >= 27 * N) return;
    int r = idx / N;
    float v = ob[r];
    for (int s = 0; s < S; ++s)
        v += P[(size_t)s * 27 * N + idx];
    if (r >= 18)
        v = 1.f / (1.f + expf(-v));
    off[idx] = v;
}

__global__ void reduce_main_kernel(const float* __restrict__ P,
                                   const float* __restrict__ bias,
                                   float* __restrict__ out, int N, int HW, int S)
{
    int idx = blockIdx.x * blockDim.x + threadIdx.x;
    if (idx >= COUT * N) return;
    int row = idx / N;
    int col = idx - row * N;
    float v = bias[row];
    for (int s = 0; s < S; ++s)
        v += P[(size_t)s * COUT * N + idx];
    int bb = col / HW;
    int hw = col - bb * HW;
    out[((size_t)bb * COUT + row) * HW + hw] = v;
}

// ---------------------------------------------------------------------------
// Host side
// ---------------------------------------------------------------------------
extern "C" void kernel_launch(void* const* d_in, const int* in_sizes, int n_in,
                              void* d_out, int out_size)
{
    const float* xs[4]  = {nullptr, nullptr, nullptr, nullptr};
    const float* ws[4]  = {nullptr, nullptr, nullptr, nullptr};
    const float* bs[4]  = {nullptr, nullptr, nullptr, nullptr};
    const float* ows[3] = {nullptr, nullptr, nullptr};
    const float* obs[3] = {nullptr, nullptr, nullptr};
    int wi = 0, bi = 0, owi = 0, obi = 0;
    for (int i = 0; i < n_in; ++i) {
        const float* p = (const float*)d_in[i];
        switch (in_sizes[i]) {
            case 2 * 256 * 96 * 96: xs[0] = p; break;
            case 2 * 256 * 48 * 48: xs[1] = p; break;
            case 2 * 256 * 24 * 24: xs[2] = p; break;
            case 2 * 256 * 12 * 12: xs[3] = p; break;
            case 256 * 256 * 3 * 3: if (wi  < 4) ws[wi++]   = p; break;
            case 256:               if (bi  < 4) bs[bi++]   = p; break;
            case 27 * 256 * 3 * 3:  if (owi < 3) ows[owi++] = p; break;
            case 27:                if (obi < 3) obs[obi++] = p; break;
            default: break;
        }
    }

    float* out = (float*)d_out;
    float* s;    cudaGetSymbolAddress((void**)&s,    g_s);
    float* off;  cudaGetSymbolAddress((void**)&off,  g_off);
    float* part; cudaGetSymbolAddress((void**)&part, g_part);
    __nv_bfloat16* chi;  cudaGetSymbolAddress((void**)&chi,  g_colshi);
    __nv_bfloat16* clo;  cudaGetSymbolAddress((void**)&clo,  g_colslo);
    __nv_bfloat16* whi;  cudaGetSymbolAddress((void**)&whi,  g_whi);
    __nv_bfloat16* wlo;  cudaGetSymbolAddress((void**)&wlo,  g_wlo);
    __nv_bfloat16* owhi; cudaGetSymbolAddress((void**)&owhi, g_owhi);
    __nv_bfloat16* owlo; cudaGetSymbolAddress((void**)&owlo, g_owlo);

    cudaFuncSetAttribute(gemm_kernel,
                         cudaFuncAttributeMaxDynamicSharedMemorySize, GEMM_SMEM);

    const size_t OFF0 = 0;
    const size_t OFF1 = OFF0 + (size_t)2 * 256 * 96 * 96;
    const size_t OFF2 = OFF1 + (size_t)2 * 256 * 48 * 48;
    const size_t OFF3 = OFF2 + (size_t)2 * 256 * 24 * 24;
    const size_t outOff[4] = {OFF0, OFF1, OFF2, OFF3};

    // weight splits (cheap, deterministic, every call)
    for (int i = 0; i < 4; ++i)
        wsplit_kernel<<<(256 * KK + 255) / 256, 256>>>(
            ws[i], whi + (size_t)i * 256 * KK, wlo + (size_t)i * 256 * KK,
            256 * KK);
    for (int j = 0; j < 3; ++j)
        wsplit_kernel<<<(27 * KK + 255) / 256, 256>>>(
            ows[j], owhi + (size_t)j * 27 * KK, owlo + (size_t)j * 27 * KK,
            27 * KK);

    const int Hs[4]    = {96, 48, 24, 12};
    // split-K (divide 72): tuned for ~150-290 CTAs/launch, g_part <= 6M floats
    const int mainS[4] = {1, 4, 18, 36};
    const int offS[4]  = {1, 8, 24, 72};

    // ---- levels 3, 2, 1: modulated deformable conv ----
    for (int lvl = 3; lvl >= 1; --lvl) {
        int H = Hs[lvl], W = H;
        int HW = H * W;
        int N = 2 * HW;
        int nTiles = (N + 127) / 128;

        const float* sin;
        if (lvl == 3) {
            sin = xs[3];
        } else {
            int total = 2 * CIN * HW;
            addup_kernel<<<(total + 255) / 256, 256>>>(
                xs[lvl], out + outOff[lvl + 1], s, H, W);
            sin = s;
        }

        // offset conv: im2col(bf16) -> GEMM(splitK) -> reduce(+sigmoid)
        im2col_kernel<<<(CIN * N + 255) / 256, 256>>>(sin, chi, clo, H, W, N);
        {
            int S = offS[lvl];
            dim3 grid(1, nTiles, S);
            gemm_kernel<<<grid, 256, GEMM_SMEM>>>(
                owhi + (size_t)(lvl - 1) * 27 * KK,
                owlo + (size_t)(lvl - 1) * 27 * KK,
                chi, clo, obs[lvl - 1], part, 27, N, HW, S);
            reduce_off_kernel<<<(27 * N + 255) / 256, 256>>>(
                part, obs[lvl - 1], off, N, S);
        }

        // main conv: dcols(bf16) -> GEMM(splitK) -> reduce(NCHW)
        dcols_kernel<<<(CIN * N + 255) / 256, 256>>>(sin, off, chi, clo, H, W, N);
        {
            int S = mainS[lvl];
            dim3 grid(2, nTiles, S);
            gemm_kernel<<<grid, 256, GEMM_SMEM>>>(
                whi + (size_t)lvl * 256 * KK, wlo + (size_t)lvl * 256 * KK,
                chi, clo, bs[lvl], part, COUT, N, HW, S);
            reduce_main_kernel<<<(COUT * N + 255) / 256, 256>>>(
                part, bs[lvl], out + outOff[lvl], N, HW, S);
        }
    }

    // ---- level 0: plain conv, fused epilogue (grid (2,144), S=1) ----
    {
        int H = 96, W = 96, HW = H * W, N = 2 * HW;
        int total = 2 * CIN * HW;
        addup_kernel<<<(total + 255) / 256, 256>>>(xs[0], out + OFF1, s, H, W);
        im2col_kernel<<<(CIN * N + 255) / 256, 256>>>(s, chi, clo, H, W, N);
        dim3 grid(2, (N + 127) / 128, 1);
        gemm_kernel<<<grid, 256, GEMM_SMEM>>>(
            whi, wlo, chi, clo, bs[0], out + OFF0, COUT, N, HW, 1);
    }
}